// round 1
// baseline (speedup 1.0000x reference)
#include <cuda_runtime.h>
#include <math.h>

// Scratch for precomputed pair-group coefficients.
// Layout: A[(g*4+p)*N + row], g in [0,8), p in [0,4).
#define MAXROWS 4096
__device__ float g_A[32 * MAXROWS];
__device__ float g_B[32 * MAXROWS];

// ---------------------------------------------------------------------------
// Precompute: for each row r and wire-pair g (wires 2g, 2g+1):
//   A[r][g] = (c0*c1, c0*s1, s0*c1, s0*s1) with c=cos(x/2), s=sin(x/2)
// Then cos((x0-y0)/2)*cos((x1-y1)/2) = dot4(A[i][g], B[j][g]).
// ---------------------------------------------------------------------------
__global__ void qk_precompute(const float* __restrict__ x,
                              const float* __restrict__ y,
                              int n, int m, int d) {
    int tid = blockIdx.x * blockDim.x + threadIdx.x;
    int total = (n + m) * 8;
    if (tid >= total) return;
    int g = tid & 7;
    int r = tid >> 3;
    const float* src;
    float* dst;
    int N;
    if (r < n) {
        src = x + (size_t)r * d;
        dst = g_A;
        N = n;
    } else {
        r -= n;
        src = y + (size_t)r * d;
        dst = g_B;
        N = m;
    }
    float s0, c0, s1, c1;
    sincosf(0.5f * src[2 * g],     &s0, &c0);
    sincosf(0.5f * src[2 * g + 1], &s1, &c1);
    dst[(g * 4 + 0) * N + r] = c0 * c1;
    dst[(g * 4 + 1) * N + r] = c0 * s1;
    dst[(g * 4 + 2) * N + r] = s0 * c1;
    dst[(g * 4 + 3) * N + r] = s0 * s1;
}

// ---------------------------------------------------------------------------
// Main product kernel: 64x64 output tile per CTA, 256 threads, 4x4 per thread.
// out[i,j] = | prod_g dot4(A[i][g], B[j][g]) |
// ---------------------------------------------------------------------------
__global__ __launch_bounds__(256, 4)
void qk_prod(float* __restrict__ out, int n, int m) {
    __shared__ float As[32][64];  // [g*4+p][i_local]
    __shared__ float Bs[32][64];  // [g*4+p][j_local]

    const int i_base = blockIdx.y * 64;
    const int j_base = blockIdx.x * 64;
    const int tid = threadIdx.x;

    // Fill smem: 32 slices x 64 floats each for A and B (coalesced float4).
    #pragma unroll
    for (int idx = tid; idx < 512; idx += 256) {
        int slice = idx >> 4;            // 0..31
        int pos = (idx & 15) << 2;       // 0,4,...,60
        *(float4*)&As[slice][pos] =
            *(const float4*)&g_A[(size_t)slice * n + i_base + pos];
        *(float4*)&Bs[slice][pos] =
            *(const float4*)&g_B[(size_t)slice * m + j_base + pos];
    }
    __syncthreads();

    const int tx = tid & 15;       // j direction
    const int ty = tid >> 4;       // i direction
    const int i0 = ty * 4;
    const int j0 = tx * 4;

    float prod[4][4];
    #pragma unroll
    for (int ii = 0; ii < 4; ii++)
        #pragma unroll
        for (int jj = 0; jj < 4; jj++)
            prod[ii][jj] = 1.0f;

    #pragma unroll
    for (int g = 0; g < 8; g++) {
        float a[4][4], b[4][4];
        #pragma unroll
        for (int p = 0; p < 4; p++) {
            float4 av = *(const float4*)&As[g * 4 + p][i0];  // broadcast in-warp
            a[p][0] = av.x; a[p][1] = av.y; a[p][2] = av.z; a[p][3] = av.w;
            float4 bv = *(const float4*)&Bs[g * 4 + p][j0];  // conflict-free
            b[p][0] = bv.x; b[p][1] = bv.y; b[p][2] = bv.z; b[p][3] = bv.w;
        }
        #pragma unroll
        for (int ii = 0; ii < 4; ii++) {
            #pragma unroll
            for (int jj = 0; jj < 4; jj++) {
                float t = a[0][ii] * b[0][jj];
                t = fmaf(a[1][ii], b[1][jj], t);
                t = fmaf(a[2][ii], b[2][jj], t);
                t = fmaf(a[3][ii], b[3][jj], t);
                prod[ii][jj] *= t;
            }
        }
    }

    #pragma unroll
    for (int ii = 0; ii < 4; ii++) {
        float4 v;
        v.x = fabsf(prod[ii][0]);
        v.y = fabsf(prod[ii][1]);
        v.z = fabsf(prod[ii][2]);
        v.w = fabsf(prod[ii][3]);
        *(float4*)&out[(size_t)(i_base + i0 + ii) * m + (j_base + j0)] = v;
    }
}

// ---------------------------------------------------------------------------
// Generic fallback (shape-robust, slow): one thread per output.
// ---------------------------------------------------------------------------
__global__ void qk_generic(const float* __restrict__ x, const float* __restrict__ y,
                           float* __restrict__ out, int n, int m, int d) {
    long long idx = (long long)blockIdx.x * blockDim.x + threadIdx.x;
    long long total = (long long)n * m;
    if (idx >= total) return;
    int i = (int)(idx / m);
    int j = (int)(idx % m);
    float prod = 1.0f;
    for (int k = 0; k < d; k++)
        prod *= cosf(0.5f * (x[(size_t)i * d + k] - y[(size_t)j * d + k]));
    out[idx] = fabsf(prod);
}

extern "C" void kernel_launch(void* const* d_in, const int* in_sizes, int n_in,
                              void* d_out, int out_size) {
    const float* x = (const float*)d_in[0];
    const float* y = (const float*)d_in[1];
    float* out = (float*)d_out;

    // Recover (n, m, d): in_sizes = {n*d, m*d}, out_size = n*m.
    double dd = sqrt((double)in_sizes[0] * (double)in_sizes[1] / (double)out_size);
    int d = (int)(dd + 0.5);
    if (d <= 0) d = 16;
    int n = in_sizes[0] / d;
    int m = in_sizes[1] / d;

    bool fast = (d == 16) && (n % 64 == 0) && (m % 64 == 0) &&
                (n <= MAXROWS) && (m <= MAXROWS) &&
                ((long long)n * d == in_sizes[0]) &&
                ((long long)m * d == in_sizes[1]) &&
                ((long long)n * m == out_size);

    if (fast) {
        int total = (n + m) * 8;
        qk_precompute<<<(total + 255) / 256, 256>>>(x, y, n, m, d);
        dim3 grid(m / 64, n / 64);
        qk_prod<<<grid, 256>>>(out, n, m);
    } else {
        long long total = (long long)n * m;
        int blocks = (int)((total + 255) / 256);
        qk_generic<<<blocks, 256>>>(x, y, out, n, m, d);
    }
}